// round 5
// baseline (speedup 1.0000x reference)
#include <cuda_runtime.h>
#include <cuda_fp16.h>
#include <cstdint>

#define S_LEN 1024
#define B_SZ  64
#define H_DIM 512

// Scratch (allocation-free rule: __device__ globals)
__device__ float g_lin[(size_t)S_LEN * B_SZ * H_DIM];  // GEMM output / scan input
__device__ float g_y0 [(size_t)S_LEN * B_SZ * H_DIM];  // layer-1 scan output
__device__ int   g_flags[128];                          // per-4-m-tile done counters

#define W_SCALE     1024.0f
#define W_SCALE_INV (1.0f / 1024.0f)

// ---------------------------------------------------------------------------
// helpers
// ---------------------------------------------------------------------------
__device__ __forceinline__ void mma_f16(float* d,
                                        uint32_t a0, uint32_t a1, uint32_t a2, uint32_t a3,
                                        uint32_t b0, uint32_t b1) {
    asm volatile(
        "mma.sync.aligned.m16n8k16.row.col.f32.f16.f16.f32 "
        "{%0,%1,%2,%3}, {%4,%5,%6,%7}, {%8,%9}, {%0,%1,%2,%3};\n"
        : "+f"(d[0]), "+f"(d[1]), "+f"(d[2]), "+f"(d[3])
        : "r"(a0), "r"(a1), "r"(a2), "r"(a3), "r"(b0), "r"(b1));
}

#define LDSM_X4(r0, r1, r2, r3, addr)                                          \
    asm volatile("ldmatrix.sync.aligned.m8n8.x4.shared.b16 {%0,%1,%2,%3}, [%4];" \
                 : "=r"(r0), "=r"(r1), "=r"(r2), "=r"(r3) : "r"(addr))

__device__ __forceinline__ uint32_t smem_u32(const void* p) {
    uint32_t a;
    asm("{ .reg .u64 t; cvta.to.shared.u64 t, %1; cvt.u32.u64 %0, t; }"
        : "=r"(a) : "l"(p));
    return a;
}

__device__ __forceinline__ uint32_t pack_h2(float a, float b) {
    __half2 h = __floats2half2_rn(a, b);
    return *reinterpret_cast<uint32_t*>(&h);
}

// split (x,y) into packed fp16 hi pair + fp16 lo pair
__device__ __forceinline__ void split2(float x, float y, uint32_t& hi, uint32_t& lo) {
    float hx = __half2float(__float2half_rn(x));
    float hy = __half2float(__float2half_rn(y));
    hi = pack_h2(hx, hy);
    lo = pack_h2(x - hx, y - hy);
}

// 8 floats (two float4) -> one 16B hi chunk + one 16B lo chunk
__device__ __forceinline__ void cvt_chunk(const float4& u, const float4& v,
                                          uint4& hi, uint4& lo) {
    split2(u.x, u.y, hi.x, lo.x);
    split2(u.z, u.w, hi.y, lo.y);
    split2(v.x, v.y, hi.z, lo.z);
    split2(v.z, v.w, hi.w, lo.w);
}

__device__ __forceinline__ void wait_group(const int* p) {
    int v;
    while (true) {
        asm volatile("ld.acquire.gpu.b32 %0, [%1];" : "=r"(v) : "l"(p) : "memory");
        if (v >= 32) return;
        __nanosleep(128);
    }
}

// ---------------------------------------------------------------------------
// Combined per-layer kernel.
// bids [0,64)    : scan role (one warp per batch row), waits on g_flags
// bids [64,4160) : GEMM role: C[m][n] = sum_k A[m][k]*W[n][k] + bias[n]
//                  fp16x3 (W pre-scaled by 1024), ldmatrix feed, 2-stage pipe.
// GEMM tile: BM=128, BN=64, BK=32; 8 warps (4x2), warp tile 32x32, m16n8k16.
// ---------------------------------------------------------------------------
#define STG_BYTES 24576
#define AHI_OFF   0
#define ALO_OFF   8192
#define WHI_OFF   16384
#define WLO_OFF   20480

__global__ __launch_bounds__(256, 2) void layer_kernel(
    const float* __restrict__ A_ext,
    const float* __restrict__ W,
    const float* __restrict__ bias,
    const float* __restrict__ rec,
    const float* __restrict__ gam,
    const float* __restrict__ bet,
    float* __restrict__ y_ext,
    float* __restrict__ hid,
    int use_y0, int to_y0, int layer)
{
    const int S = S_LEN, B = B_SZ, K = H_DIM, N = H_DIM;

    if (blockIdx.x >= 64) {
        // =================== GEMM role ===================
        __shared__ __align__(128) char smbuf[2][STG_BYTES];

        const float* A = use_y0 ? g_y0 : A_ext;
        float* C = g_lin;

        int gb = blockIdx.x - 64;
        int nb = gb & 7;            // n fastest -> A-slice reuse in L2
        int mt = gb >> 3;
        int n0 = nb * 64, m0 = mt * 128;

        int tid  = threadIdx.x;
        int warp = tid >> 5, lane = tid & 31;
        int wm = warp & 3, wn = warp >> 2;

        uint32_t smb = smem_u32(smbuf);

        // loader mapping
        int ldA_row  = tid >> 1;          // 0..127
        int ldA_half = tid & 1;           // 16-float half of the 32-k stage
        int ldW_row  = tid >> 2;          // 0..63
        int ldW_q    = tid & 3;           // 8-float quarter

        const float* Aptr = A + (size_t)(m0 + ldA_row) * K + ldA_half * 16;
        const float* Wptr = W + (size_t)(n0 + ldW_row) * K + ldW_q * 8;

        // STS byte offsets (within a stage), swizzle: chunk ^= (row>>1)&3
        uint32_t aswzL = (ldA_row >> 1) & 3;
        uint32_t stsA0 = (uint32_t)ldA_row * 64 + (((ldA_half * 2 + 0) ^ aswzL) << 4);
        uint32_t stsA1 = (uint32_t)ldA_row * 64 + (((ldA_half * 2 + 1) ^ aswzL) << 4);
        uint32_t stsW  = (uint32_t)ldW_row * 64 + (((uint32_t)ldW_q ^ ((ldW_row >> 1) & 3)) << 4);

        // LDSM per-lane invariants
        int aRowIn = (lane & 7) + ((lane >> 3) & 1) * 8;
        uint32_t aKsel = (uint32_t)(lane >> 4);
        uint32_t aRowTerm[2], aSwz[2];
#pragma unroll
        for (int m2 = 0; m2 < 2; m2++) {
            int row = wm * 32 + m2 * 16 + aRowIn;
            aRowTerm[m2] = (uint32_t)row * 64;
            aSwz[m2] = (row >> 1) & 3;
        }
        int bRowIn = (lane & 7) + ((lane >> 4) & 1) * 8;
        uint32_t bKsel = (uint32_t)((lane >> 3) & 1);
        uint32_t bRowTerm[2], bSwz[2];
#pragma unroll
        for (int p = 0; p < 2; p++) {
            int row = wn * 32 + p * 16 + bRowIn;
            bRowTerm[p] = (uint32_t)row * 64;
            bSwz[p] = (row >> 1) & 3;
        }

        float acc[2][4][4];
#pragma unroll
        for (int m2 = 0; m2 < 2; m2++)
#pragma unroll
            for (int nt = 0; nt < 4; nt++)
#pragma unroll
                for (int i = 0; i < 4; i++) acc[m2][nt][i] = 0.0f;

        // register staging for one stage
        float4 ra0, ra1, ra2, ra3, rw0, rw1;

        // prologue: LDG stage 0
        ra0 = *reinterpret_cast<const float4*>(Aptr + 0);
        ra1 = *reinterpret_cast<const float4*>(Aptr + 4);
        ra2 = *reinterpret_cast<const float4*>(Aptr + 8);
        ra3 = *reinterpret_cast<const float4*>(Aptr + 12);
        rw0 = *reinterpret_cast<const float4*>(Wptr + 0);
        rw1 = *reinterpret_cast<const float4*>(Wptr + 4);

        for (int it = 0; it < 16; ++it) {
            int buf = it & 1;
            char* st = smbuf[buf];

            // STS stage it from staged regs
            {
                uint4 hi, lo;
                cvt_chunk(ra0, ra1, hi, lo);
                *reinterpret_cast<uint4*>(st + AHI_OFF + stsA0) = hi;
                *reinterpret_cast<uint4*>(st + ALO_OFF + stsA0) = lo;
                cvt_chunk(ra2, ra3, hi, lo);
                *reinterpret_cast<uint4*>(st + AHI_OFF + stsA1) = hi;
                *reinterpret_cast<uint4*>(st + ALO_OFF + stsA1) = lo;
                float4 w0 = make_float4(rw0.x * W_SCALE, rw0.y * W_SCALE,
                                        rw0.z * W_SCALE, rw0.w * W_SCALE);
                float4 w1 = make_float4(rw1.x * W_SCALE, rw1.y * W_SCALE,
                                        rw1.z * W_SCALE, rw1.w * W_SCALE);
                cvt_chunk(w0, w1, hi, lo);
                *reinterpret_cast<uint4*>(st + WHI_OFF + stsW) = hi;
                *reinterpret_cast<uint4*>(st + WLO_OFF + stsW) = lo;
            }
            __syncthreads();

            // LDG stage it+1 (consumed at next iteration's STS)
            if (it < 15) {
                int kt = (it + 1) * 32;
                ra0 = *reinterpret_cast<const float4*>(Aptr + kt + 0);
                ra1 = *reinterpret_cast<const float4*>(Aptr + kt + 4);
                ra2 = *reinterpret_cast<const float4*>(Aptr + kt + 8);
                ra3 = *reinterpret_cast<const float4*>(Aptr + kt + 12);
                rw0 = *reinterpret_cast<const float4*>(Wptr + kt + 0);
                rw1 = *reinterpret_cast<const float4*>(Wptr + kt + 4);
            }

            // MMA on stage it
            uint32_t bbase = smb + (uint32_t)buf * STG_BYTES;
#pragma unroll
            for (int kk = 0; kk < 2; ++kk) {
                uint32_t ah[2][4], al[2][4], bh[2][4], bl[2][4];
#pragma unroll
                for (int m2 = 0; m2 < 2; m2++) {
                    uint32_t tail = aRowTerm[m2] + ((((uint32_t)kk * 2 + aKsel) ^ aSwz[m2]) << 4);
                    LDSM_X4(ah[m2][0], ah[m2][1], ah[m2][2], ah[m2][3],
                            bbase + AHI_OFF + tail);
                    LDSM_X4(al[m2][0], al[m2][1], al[m2][2], al[m2][3],
                            bbase + ALO_OFF + tail);
                }
#pragma unroll
                for (int p = 0; p < 2; p++) {
                    uint32_t tail = bRowTerm[p] + ((((uint32_t)kk * 2 + bKsel) ^ bSwz[p]) << 4);
                    LDSM_X4(bh[p][0], bh[p][1], bh[p][2], bh[p][3],
                            bbase + WHI_OFF + tail);
                    LDSM_X4(bl[p][0], bl[p][1], bl[p][2], bl[p][3],
                            bbase + WLO_OFF + tail);
                }
#pragma unroll
                for (int m2 = 0; m2 < 2; m2++) {
#pragma unroll
                    for (int nt = 0; nt < 4; nt++) {
                        int p = nt >> 1, q = nt & 1;
                        uint32_t bf0 = bh[p][2 * q], bf1 = bh[p][2 * q + 1];
                        uint32_t bg0 = bl[p][2 * q], bg1 = bl[p][2 * q + 1];
                        mma_f16(acc[m2][nt], al[m2][0], al[m2][1], al[m2][2], al[m2][3], bf0, bf1);
                        mma_f16(acc[m2][nt], ah[m2][0], ah[m2][1], ah[m2][2], ah[m2][3], bg0, bg1);
                        mma_f16(acc[m2][nt], ah[m2][0], ah[m2][1], ah[m2][2], ah[m2][3], bf0, bf1);
                    }
                }
            }
            __syncthreads();
        }

        // epilogue: unscale, add bias, store
        int r = lane >> 2, c = lane & 3;
#pragma unroll
        for (int m2 = 0; m2 < 2; m2++) {
#pragma unroll
            for (int nt = 0; nt < 4; nt++) {
                int row = m0 + wm * 32 + m2 * 16 + r;
                int col = n0 + wn * 32 + (nt >> 1) * 16 + (nt & 1) * 8 + 2 * c;
                float bx = bias[col], by = bias[col + 1];
                *reinterpret_cast<float2*>(C + (size_t)row * N + col) = make_float2(
                    fmaf(acc[m2][nt][0], W_SCALE_INV, bx),
                    fmaf(acc[m2][nt][1], W_SCALE_INV, by));
                *reinterpret_cast<float2*>(C + (size_t)(row + 8) * N + col) = make_float2(
                    fmaf(acc[m2][nt][2], W_SCALE_INV, bx),
                    fmaf(acc[m2][nt][3], W_SCALE_INV, by));
            }
        }

        __syncthreads();
        if (tid == 0) {
            __threadfence();
            atomicAdd(&g_flags[mt >> 2], 1);  // 4 m-tiles x 8 n-blocks = 32
        }
        return;
    }

    // =================== scan role ===================
    if (threadIdx.x >= 32) return;

    int b = blockIdx.x, lane = threadIdx.x;
    int base = lane * 16;

    const float* lin = g_lin;
    float* y = to_y0 ? g_y0 : y_ext;

    float rc[16], ga[16], bb[16], h[16];
#pragma unroll
    for (int q = 0; q < 4; q++) {
        float4 v;
        v = *reinterpret_cast<const float4*>(rec + base + q * 4);
        rc[q*4] = v.x; rc[q*4+1] = v.y; rc[q*4+2] = v.z; rc[q*4+3] = v.w;
        v = *reinterpret_cast<const float4*>(gam + base + q * 4);
        ga[q*4] = v.x; ga[q*4+1] = v.y; ga[q*4+2] = v.z; ga[q*4+3] = v.w;
        v = *reinterpret_cast<const float4*>(bet + base + q * 4);
        bb[q*4] = v.x; bb[q*4+1] = v.y; bb[q*4+2] = v.z; bb[q*4+3] = v.w;
    }
#pragma unroll
    for (int j = 0; j < 16; j++) h[j] = 0.0f;

    const size_t stride = (size_t)B * H_DIM;
    const float* lp = lin + (size_t)b * H_DIM + base;
    float*       yp = y   + (size_t)b * H_DIM + base;

    // wait for first tile group (timesteps 0..7), then prime depth-2 pipeline
    wait_group(&g_flags[0]);
    float cuA[16], cuB[16];
#pragma unroll
    for (int q = 0; q < 4; q++) {
        float4 v = __ldcg(reinterpret_cast<const float4*>(lp + q * 4));
        cuA[q*4] = v.x; cuA[q*4+1] = v.y; cuA[q*4+2] = v.z; cuA[q*4+3] = v.w;
        v = __ldcg(reinterpret_cast<const float4*>(lp + stride + q * 4));
        cuB[q*4] = v.x; cuB[q*4+1] = v.y; cuB[q*4+2] = v.z; cuB[q*4+3] = v.w;
    }

#define SCAN_STEP(scur, CU)                                                        \
  {                                                                                \
    _Pragma("unroll")                                                              \
    for (int j = 0; j < 16; j++) h[j] = fmaf(rc[j], h[j], CU[j]);                  \
    {                                                                              \
      int sp = (scur) + 2;                                                         \
      if (sp < S && (sp & 7) == 0) wait_group(&g_flags[sp >> 3]);                  \
      if (sp > S - 1) sp = S - 1;                                                  \
      const float* p2 = lp + (size_t)sp * stride;                                  \
      _Pragma("unroll")                                                            \
      for (int q = 0; q < 4; q++) {                                                \
        float4 v = __ldcg(reinterpret_cast<const float4*>(p2 + q * 4));            \
        CU[q*4+0] = v.x; CU[q*4+1] = v.y; CU[q*4+2] = v.z; CU[q*4+3] = v.w;        \
      }                                                                            \
    }                                                                              \
    float ts[8], tq[8];                                                            \
    _Pragma("unroll")                                                              \
    for (int j = 0; j < 8; j++) {                                                  \
      ts[j] = h[j] + h[j + 8];                                                     \
      tq[j] = fmaf(h[j], h[j], h[j + 8] * h[j + 8]);                               \
    }                                                                              \
    _Pragma("unroll")                                                              \
    for (int w = 4; w >= 1; w >>= 1) {                                             \
      _Pragma("unroll")                                                            \
      for (int j = 0; j < w; j++) { ts[j] += ts[j+w]; tq[j] += tq[j+w]; }          \
    }                                                                              \
    float sum = ts[0], ssq = tq[0];                                                \
    _Pragma("unroll")                                                              \
    for (int off = 16; off >= 1; off >>= 1) {                                      \
      sum += __shfl_xor_sync(0xffffffffu, sum, off);                               \
      ssq += __shfl_xor_sync(0xffffffffu, ssq, off);                               \
    }                                                                              \
    float mean = sum * (1.0f / H_DIM);                                             \
    float var  = fmaf(ssq, 1.0f / H_DIM, -mean * mean);                            \
    float inv  = rsqrtf(var + 1e-6f);                                              \
    _Pragma("unroll")                                                              \
    for (int j = 0; j < 16; j++) {                                                 \
      float o = fmaf((h[j] - mean) * inv, ga[j], bb[j]);                           \
      o = fminf(fmaxf(o, 0.0f), 6.0f);                                             \
      h[j] = o;                                                                    \
    }                                                                              \
    {                                                                              \
      float* yo = yp + (size_t)(scur) * stride;                                    \
      _Pragma("unroll")                                                            \
      for (int q = 0; q < 4; q++)                                                  \
        *reinterpret_cast<float4*>(yo + q * 4) =                                   \
            make_float4(h[q*4], h[q*4+1], h[q*4+2], h[q*4+3]);                     \
    }                                                                              \
  }

    for (int s = 0; s < S; s += 2) {
        SCAN_STEP(s,     cuA);
        SCAN_STEP(s + 1, cuB);
    }

    // hiddens: ref does cat(dim=-1).view(2,B,H) ->
    // hid[(b>>5)][2*(b&31)+layer][h] = h_last[b][h]
    float* hp = hid + (size_t)(b >> 5) * (B * H_DIM)
                    + (size_t)(2 * (b & 31) + layer) * H_DIM + base;
#pragma unroll
    for (int q = 0; q < 4; q++)
        *reinterpret_cast<float4*>(hp + q * 4) =
            make_float4(h[q*4], h[q*4+1], h[q*4+2], h[q*4+3]);
}

// ---------------------------------------------------------------------------
// flag reset (must run before each layer_kernel; graph replays reuse state)
// ---------------------------------------------------------------------------
__global__ void zero_flags_kernel() {
    g_flags[threadIdx.x] = 0;
}

// ---------------------------------------------------------------------------
// launcher
// ---------------------------------------------------------------------------
extern "C" void kernel_launch(void* const* d_in, const int* in_sizes, int n_in,
                              void* d_out, int out_size)
{
    (void)n_in; (void)out_size; (void)in_sizes;
    const float* x    = (const float*)d_in[0];
    const float* W0   = (const float*)d_in[1];
    const float* b0   = (const float*)d_in[2];
    const float* rec0 = (const float*)d_in[3];
    const float* g0   = (const float*)d_in[4];
    const float* be0  = (const float*)d_in[5];
    const float* W1   = (const float*)d_in[6];
    const float* b1   = (const float*)d_in[7];
    const float* rec1 = (const float*)d_in[8];
    const float* g1   = (const float*)d_in[9];
    const float* be1  = (const float*)d_in[10];

    float* out = (float*)d_out;
    float* hid = out + (size_t)S_LEN * B_SZ * H_DIM;

    const int GRID = 64 + (S_LEN * B_SZ / 128) * (H_DIM / 64);  // 64 + 4096

    // layer 1
    zero_flags_kernel<<<1, 128>>>();
    layer_kernel<<<GRID, 256>>>(x, W0, b0, rec0, g0, be0,
                                nullptr, hid, /*use_y0=*/0, /*to_y0=*/1, /*layer=*/0);
    // layer 2
    zero_flags_kernel<<<1, 128>>>();
    layer_kernel<<<GRID, 256>>>(nullptr, W1, b1, rec1, g1, be1,
                                out, hid, /*use_y0=*/1, /*to_y0=*/0, /*layer=*/1);
}

// round 6
// speedup vs baseline: 1.1902x; 1.1902x over previous
#include <cuda_runtime.h>
#include <cuda_fp16.h>
#include <cstdint>

#define S_LEN 1024
#define B_SZ  64
#define H_DIM 512

// Scratch (allocation-free rule: __device__ globals)
__device__ float g_lin[(size_t)S_LEN * B_SZ * H_DIM];  // GEMM output / scan input
__device__ float g_y0 [(size_t)S_LEN * B_SZ * H_DIM];  // layer-1 scan output
__device__ int   g_flags[128];                          // per-4-m-tile done counters

#define W_SCALE     1024.0f
#define W_SCALE_INV (1.0f / 1024.0f)

// ---------------------------------------------------------------------------
// helpers
// ---------------------------------------------------------------------------
__device__ __forceinline__ void mma_f16(float* d, const uint32_t* a, const uint32_t* b) {
    asm volatile(
        "mma.sync.aligned.m16n8k16.row.col.f32.f16.f16.f32 "
        "{%0,%1,%2,%3}, {%4,%5,%6,%7}, {%8,%9}, {%0,%1,%2,%3};\n"
        : "+f"(d[0]), "+f"(d[1]), "+f"(d[2]), "+f"(d[3])
        : "r"(a[0]), "r"(a[1]), "r"(a[2]), "r"(a[3]),
          "r"(b[0]), "r"(b[1]));
}

__device__ __forceinline__ uint32_t pack_h2(float a, float b) {
    __half2 h = __floats2half2_rn(a, b);
    return *reinterpret_cast<uint32_t*>(&h);
}

// split (x,y) into packed fp16 hi pair + fp16 lo pair
__device__ __forceinline__ void split2(float x, float y, uint32_t& hi, uint32_t& lo) {
    float hx = __half2float(__float2half_rn(x));
    float hy = __half2float(__float2half_rn(y));
    hi = pack_h2(hx, hy);
    lo = pack_h2(x - hx, y - hy);
}

__device__ __forceinline__ void wait_group(const int* p) {
    int v;
    while (true) {
        asm volatile("ld.acquire.gpu.b32 %0, [%1];" : "=r"(v) : "l"(p) : "memory");
        if (v >= 32) return;
        __nanosleep(128);
    }
}

// double-buffered stage layout (dynamic smem)
struct Stage {
    uint32_t As_hi[128][20];
    uint32_t As_lo[128][20];
    uint32_t Bs_hi[64][20];
    uint32_t Bs_lo[64][20];
};
#define SMEM_DYN (2 * sizeof(Stage))   // 61440 B

// ---------------------------------------------------------------------------
// Combined per-layer kernel.
// bids [0,64)    : scan role (one warp per batch row), waits on g_flags
// bids [64,4160) : GEMM role: C[m][n] = sum_k A[m][k]*W[n][k] + bias[n]
//                  fp16x3 (W pre-scaled by 1024), double-buffered stages,
//                  one __syncthreads per K-iteration.
// GEMM tile: BM=128, BN=64, BK=32; 8 warps (4x2), warp tile 32x32, m16n8k16.
// ---------------------------------------------------------------------------
__global__ __launch_bounds__(256, 2) void layer_kernel(
    const float* __restrict__ A_ext,
    const float* __restrict__ W,
    const float* __restrict__ bias,
    const float* __restrict__ rec,
    const float* __restrict__ gam,
    const float* __restrict__ bet,
    float* __restrict__ y_ext,
    float* __restrict__ hid,
    int use_y0, int to_y0, int layer)
{
    const int S = S_LEN, B = B_SZ, K = H_DIM, N = H_DIM;

    if (blockIdx.x >= 64) {
        // =================== GEMM role ===================
        extern __shared__ __align__(16) char dynsm[];
        Stage* stages = reinterpret_cast<Stage*>(dynsm);

        const float* A = use_y0 ? g_y0 : A_ext;
        float* C = g_lin;

        int gb = blockIdx.x - 64;
        int nb = gb & 7;            // n fastest -> A-slice reuse in L2
        int mt = gb >> 3;
        int n0 = nb * 64, m0 = mt * 128;

        int tid  = threadIdx.x;
        int warp = tid >> 5, lane = tid & 31;
        int wm = warp & 3, wn = warp >> 2;
        int r = lane >> 2, c = lane & 3;

        float acc[2][4][4];
#pragma unroll
        for (int mtt = 0; mtt < 2; mtt++)
#pragma unroll
            for (int nt = 0; nt < 4; nt++)
#pragma unroll
                for (int i = 0; i < 4; i++) acc[mtt][nt][i] = 0.0f;

        const float* Ab = A + (size_t)m0 * K;
        const float* Wb = W + (size_t)n0 * K;

        // ---- load one K-stage (LDG + cvt + STS, no sync) ----
        auto load_stage = [&](Stage* st, int kt) {
            // A tile: 128 rows x 32 floats = 1024 float4; 4 per thread
#pragma unroll
            for (int i = 0; i < 4; i++) {
                int idx = tid + i * 256;
                int row = idx >> 3;
                int c4  = idx & 7;
                float4 v = *reinterpret_cast<const float4*>(Ab + (size_t)row * K + kt + c4 * 4);
                uint32_t h0, l0, h1, l1;
                split2(v.x, v.y, h0, l0);
                split2(v.z, v.w, h1, l1);
                st->As_hi[row][c4 * 2] = h0;  st->As_hi[row][c4 * 2 + 1] = h1;
                st->As_lo[row][c4 * 2] = l0;  st->As_lo[row][c4 * 2 + 1] = l1;
            }
            // W tile: 64 rows x 32 floats = 512 float4; 2 per thread (scaled)
#pragma unroll
            for (int i = 0; i < 2; i++) {
                int idx = tid + i * 256;
                int row = idx >> 3;
                int c4  = idx & 7;
                float4 v = *reinterpret_cast<const float4*>(Wb + (size_t)row * K + kt + c4 * 4);
                uint32_t h0, l0, h1, l1;
                split2(v.x * W_SCALE, v.y * W_SCALE, h0, l0);
                split2(v.z * W_SCALE, v.w * W_SCALE, h1, l1);
                st->Bs_hi[row][c4 * 2] = h0;  st->Bs_hi[row][c4 * 2 + 1] = h1;
                st->Bs_lo[row][c4 * 2] = l0;  st->Bs_lo[row][c4 * 2 + 1] = l1;
            }
        };

        // prologue: stage 0
        load_stage(&stages[0], 0);
        __syncthreads();

        for (int it = 0; it < 16; ++it) {
            // load next stage into the other buffer (no barrier needed here:
            // buf^1 was last read in MMA(it-1), protected by previous sync)
            if (it < 15) load_stage(&stages[(it + 1) & 1], (it + 1) * 32);

            // MMA on current stage
            Stage* cs = &stages[it & 1];
#pragma unroll
            for (int kk = 0; kk < 2; kk++) {
                int kb = kk * 8;
                uint32_t ah[2][4], al[2][4], bh[4][2], bl[4][2];
#pragma unroll
                for (int mtt = 0; mtt < 2; mtt++) {
                    int row = wm * 32 + mtt * 16 + r;
                    ah[mtt][0] = cs->As_hi[row    ][kb + c    ];
                    ah[mtt][1] = cs->As_hi[row + 8][kb + c    ];
                    ah[mtt][2] = cs->As_hi[row    ][kb + c + 4];
                    ah[mtt][3] = cs->As_hi[row + 8][kb + c + 4];
                    al[mtt][0] = cs->As_lo[row    ][kb + c    ];
                    al[mtt][1] = cs->As_lo[row + 8][kb + c    ];
                    al[mtt][2] = cs->As_lo[row    ][kb + c + 4];
                    al[mtt][3] = cs->As_lo[row + 8][kb + c + 4];
                }
#pragma unroll
                for (int nt = 0; nt < 4; nt++) {
                    int nrow = wn * 32 + nt * 8 + r;
                    bh[nt][0] = cs->Bs_hi[nrow][kb + c];
                    bh[nt][1] = cs->Bs_hi[nrow][kb + c + 4];
                    bl[nt][0] = cs->Bs_lo[nrow][kb + c];
                    bl[nt][1] = cs->Bs_lo[nrow][kb + c + 4];
                }
#pragma unroll
                for (int mtt = 0; mtt < 2; mtt++)
#pragma unroll
                    for (int nt = 0; nt < 4; nt++) {
                        mma_f16(acc[mtt][nt], al[mtt], bh[nt]);  // lo*hi
                        mma_f16(acc[mtt][nt], ah[mtt], bl[nt]);  // hi*lo
                        mma_f16(acc[mtt][nt], ah[mtt], bh[nt]);  // hi*hi
                    }
            }
            __syncthreads();   // one barrier per iteration
        }

        // epilogue: unscale, add bias, store
#pragma unroll
        for (int mtt = 0; mtt < 2; mtt++) {
#pragma unroll
            for (int nt = 0; nt < 4; nt++) {
                int row = m0 + wm * 32 + mtt * 16 + r;
                int col = n0 + wn * 32 + nt * 8 + 2 * c;
                float bx = bias[col], by = bias[col + 1];
                *reinterpret_cast<float2*>(C + (size_t)row * N + col) = make_float2(
                    fmaf(acc[mtt][nt][0], W_SCALE_INV, bx),
                    fmaf(acc[mtt][nt][1], W_SCALE_INV, by));
                *reinterpret_cast<float2*>(C + (size_t)(row + 8) * N + col) = make_float2(
                    fmaf(acc[mtt][nt][2], W_SCALE_INV, bx),
                    fmaf(acc[mtt][nt][3], W_SCALE_INV, by));
            }
        }

        __syncthreads();
        if (tid == 0) {
            __threadfence();
            atomicAdd(&g_flags[mt >> 2], 1);  // 4 m-tiles x 8 n-blocks = 32
        }
        return;
    }

    // =================== scan role ===================
    if (threadIdx.x >= 32) return;

    int b = blockIdx.x, lane = threadIdx.x;
    int base = lane * 16;

    const float* lin = g_lin;
    float* y = to_y0 ? g_y0 : y_ext;

    float rc[16], ga[16], bb[16], h[16];
#pragma unroll
    for (int q = 0; q < 4; q++) {
        float4 v;
        v = *reinterpret_cast<const float4*>(rec + base + q * 4);
        rc[q*4] = v.x; rc[q*4+1] = v.y; rc[q*4+2] = v.z; rc[q*4+3] = v.w;
        v = *reinterpret_cast<const float4*>(gam + base + q * 4);
        ga[q*4] = v.x; ga[q*4+1] = v.y; ga[q*4+2] = v.z; ga[q*4+3] = v.w;
        v = *reinterpret_cast<const float4*>(bet + base + q * 4);
        bb[q*4] = v.x; bb[q*4+1] = v.y; bb[q*4+2] = v.z; bb[q*4+3] = v.w;
    }
#pragma unroll
    for (int j = 0; j < 16; j++) h[j] = 0.0f;

    const size_t stride = (size_t)B * H_DIM;
    const float* lp = lin + (size_t)b * H_DIM + base;
    float*       yp = y   + (size_t)b * H_DIM + base;

    // wait for first tile group (timesteps 0..7), then prime depth-2 pipeline
    wait_group(&g_flags[0]);
    float cuA[16], cuB[16];
#pragma unroll
    for (int q = 0; q < 4; q++) {
        float4 v = __ldcg(reinterpret_cast<const float4*>(lp + q * 4));
        cuA[q*4] = v.x; cuA[q*4+1] = v.y; cuA[q*4+2] = v.z; cuA[q*4+3] = v.w;
        v = __ldcg(reinterpret_cast<const float4*>(lp + stride + q * 4));
        cuB[q*4] = v.x; cuB[q*4+1] = v.y; cuB[q*4+2] = v.z; cuB[q*4+3] = v.w;
    }

#define SCAN_STEP(scur, CU)                                                        \
  {                                                                                \
    _Pragma("unroll")                                                              \
    for (int j = 0; j < 16; j++) h[j] = fmaf(rc[j], h[j], CU[j]);                  \
    {                                                                              \
      int sp = (scur) + 2;                                                         \
      if (sp < S && (sp & 7) == 0) wait_group(&g_flags[sp >> 3]);                  \
      if (sp > S - 1) sp = S - 1;                                                  \
      const float* p2 = lp + (size_t)sp * stride;                                  \
      _Pragma("unroll")                                                            \
      for (int q = 0; q < 4; q++) {                                                \
        float4 v = __ldcg(reinterpret_cast<const float4*>(p2 + q * 4));            \
        CU[q*4+0] = v.x; CU[q*4+1] = v.y; CU[q*4+2] = v.z; CU[q*4+3] = v.w;        \
      }                                                                            \
    }                                                                              \
    float ts[8], tq[8];                                                            \
    _Pragma("unroll")                                                              \
    for (int j = 0; j < 8; j++) {                                                  \
      ts[j] = h[j] + h[j + 8];                                                     \
      tq[j] = fmaf(h[j], h[j], h[j + 8] * h[j + 8]);                               \
    }                                                                              \
    _Pragma("unroll")                                                              \
    for (int w = 4; w >= 1; w >>= 1) {                                             \
      _Pragma("unroll")                                                            \
      for (int j = 0; j < w; j++) { ts[j] += ts[j+w]; tq[j] += tq[j+w]; }          \
    }                                                                              \
    float sum = ts[0], ssq = tq[0];                                                \
    _Pragma("unroll")                                                              \
    for (int off = 16; off >= 1; off >>= 1) {                                      \
      sum += __shfl_xor_sync(0xffffffffu, sum, off);                               \
      ssq += __shfl_xor_sync(0xffffffffu, ssq, off);                               \
    }                                                                              \
    float mean = sum * (1.0f / H_DIM);                                             \
    float var  = fmaf(ssq, 1.0f / H_DIM, -mean * mean);                            \
    float inv  = rsqrtf(var + 1e-6f);                                              \
    _Pragma("unroll")                                                              \
    for (int j = 0; j < 16; j++) {                                                 \
      float o = fmaf((h[j] - mean) * inv, ga[j], bb[j]);                           \
      o = fminf(fmaxf(o, 0.0f), 6.0f);                                             \
      h[j] = o;                                                                    \
    }                                                                              \
    {                                                                              \
      float* yo = yp + (size_t)(scur) * stride;                                    \
      _Pragma("unroll")                                                            \
      for (int q = 0; q < 4; q++)                                                  \
        *reinterpret_cast<float4*>(yo + q * 4) =                                   \
            make_float4(h[q*4], h[q*4+1], h[q*4+2], h[q*4+3]);                     \
    }                                                                              \
  }

    for (int s = 0; s < S; s += 2) {
        SCAN_STEP(s,     cuA);
        SCAN_STEP(s + 1, cuB);
    }

    // hiddens: ref does cat(dim=-1).view(2,B,H) ->
    // hid[(b>>5)][2*(b&31)+layer][h] = h_last[b][h]
    float* hp = hid + (size_t)(b >> 5) * (B * H_DIM)
                    + (size_t)(2 * (b & 31) + layer) * H_DIM + base;
#pragma unroll
    for (int q = 0; q < 4; q++)
        *reinterpret_cast<float4*>(hp + q * 4) =
            make_float4(h[q*4], h[q*4+1], h[q*4+2], h[q*4+3]);
}

// ---------------------------------------------------------------------------
// flag reset (must run before each layer_kernel; graph replays reuse state)
// ---------------------------------------------------------------------------
__global__ void zero_flags_kernel() {
    g_flags[threadIdx.x] = 0;
}

// ---------------------------------------------------------------------------
// launcher
// ---------------------------------------------------------------------------
extern "C" void kernel_launch(void* const* d_in, const int* in_sizes, int n_in,
                              void* d_out, int out_size)
{
    (void)n_in; (void)out_size; (void)in_sizes;
    const float* x    = (const float*)d_in[0];
    const float* W0   = (const float*)d_in[1];
    const float* b0   = (const float*)d_in[2];
    const float* rec0 = (const float*)d_in[3];
    const float* g0   = (const float*)d_in[4];
    const float* be0  = (const float*)d_in[5];
    const float* W1   = (const float*)d_in[6];
    const float* b1   = (const float*)d_in[7];
    const float* rec1 = (const float*)d_in[8];
    const float* g1   = (const float*)d_in[9];
    const float* be1  = (const float*)d_in[10];

    float* out = (float*)d_out;
    float* hid = out + (size_t)S_LEN * B_SZ * H_DIM;

    const int GRID = 64 + (S_LEN * B_SZ / 128) * (H_DIM / 64);  // 64 + 4096

    static bool attr_set = false;
    if (!attr_set) {
        cudaFuncSetAttribute(layer_kernel,
                             cudaFuncAttributeMaxDynamicSharedMemorySize, SMEM_DYN);
        attr_set = true;
    }

    // layer 1
    zero_flags_kernel<<<1, 128>>>();
    layer_kernel<<<GRID, 256, SMEM_DYN>>>(x, W0, b0, rec0, g0, be0,
                                nullptr, hid, /*use_y0=*/0, /*to_y0=*/1, /*layer=*/0);
    // layer 2
    zero_flags_kernel<<<1, 128>>>();
    layer_kernel<<<GRID, 256, SMEM_DYN>>>(nullptr, W1, b1, rec1, g1, be1,
                                out, hid, /*use_y0=*/1, /*to_y0=*/0, /*layer=*/1);
}